// round 11
// baseline (speedup 1.0000x reference)
#include <cuda_runtime.h>

// RCLoss = mean((Gram_c(pred_patches) - Gram_c(target_patches))^2), 3x3 patches, C=256.
// Centered Gram is linear in raw Gram; raw-Gram entries are shifted samples of 13
// cross-correlation difference maps D_d = sum_c (p*p_shift - t*t_shift).
// A: corr maps; 2 channels per pipeline step (16 barriers), depth-3 cp.async.
// B: sum 8 chunk slices -> g_Dsum. C: gather+center+MSE, atomicAdd to out.

#define BATCH   4
#define CH      256
#define H       96
#define W       96
#define HW      (H*W)
#define ND      13
#define HP      94
#define WP      94
#define NCHUNK  8
#define CCHUNK  32
#define CPS     2                     // channels per pipeline step
#define NSTEP   (CCHUNK/CPS)          // 16

#define TROWS     4                   // output rows per block
#define SROWS     6                   // staged rows
#define TFLOATS   (SROWS*W)           // 576
#define TVEC      (TFLOATS/4)         // 144 float4 per tensor-channel
#define TSTRIDE   (TFLOATS+8)         // +4 front guard (16B align) +4 back
#define CHBUF     (2*CPS*TSTRIDE)     // 2 tensors x 2 channels = 2336 floats
#define DEPTH     3
#define SLOT4     (2*CPS*TVEC)        // 576 float4 slots per step
#define NJ        5                   // ceil(576/128)

#define SUM_N4   (BATCH*ND*HW/4)      // 119808 float4s

__device__ float g_D[BATCH*NCHUNK*ND*HW];     // per-chunk slices
__device__ float g_Dsum[BATCH*ND*HW];         // chunk-summed maps (1.9MB)

__device__ __forceinline__ void cp16(unsigned saddr, const float* g) {
    asm volatile("cp.async.cg.shared.global [%0], [%1], 16;\n" :: "r"(saddr), "l"(g));
}
__device__ __forceinline__ void cp_commit() {
    asm volatile("cp.async.commit_group;\n" ::: "memory");
}
template<int N> __device__ __forceinline__ void cp_wait() {
    asm volatile("cp.async.wait_group %0;\n" :: "n"(N) : "memory");
}

// ---------------------------------------------------------------------------
// Kernel A. grid (24, NCHUNK, BATCH) = 768 blocks, block (32, 4).
__global__ __launch_bounds__(128, 6)
void corr_kernel(const float* __restrict__ pred, const float* __restrict__ targ,
                 float* __restrict__ out) {
    __shared__ __align__(16) float sm[DEPTH * CHBUF];

    const int lane  = threadIdx.x;
    const int ty    = threadIdx.y;            // 0..3, warp == output row
    const int tid   = ty * 32 + lane;
    const int gy0   = blockIdx.x * TROWS;
    const int chunk = blockIdx.y;
    const int b     = blockIdx.z;

    if (tid == 0 && gy0 == 0 && chunk == 0 && b == 0) out[0] = 0.f;

    const int avail = (gy0 + SROWS <= H) ? SROWS : (H - gy0);   // 6 or 4

    if (avail < SROWS) {   // zero unused staged rows once in every region
        const int zfl = (SROWS - avail) * W;                     // 192
        for (int i = tid; i < DEPTH * 2 * CPS * zfl; i += 128) {
            int buf = i / (2 * CPS * zfl);
            int r   = i - buf * (2 * CPS * zfl);
            int reg = r / zfl;                 // 0..3 = (ch*2 + t)
            int f   = r - reg * zfl;
            sm[buf * CHBUF + reg * TSTRIDE + 4 + avail * W + f] = 0.f;
        }
    }

    // Flat staging: SLOT4=576 float4 slots per step, 128 threads, 5 slots each.
    const size_t cbase = (size_t)(b * CH + chunk * CCHUNK) * HW + (size_t)gy0 * W;
    unsigned     sof[NJ];
    const float* gp[NJ];
    bool         m[NJ];
    #pragma unroll
    for (int j = 0; j < NJ; j++) {
        int  e   = tid + 128 * j;
        int  ch  = e / (2 * TVEC);             // 0..1 channel within step
        int  rem = e - ch * (2 * TVEC);
        int  t   = (rem >= TVEC) ? 1 : 0;
        int  f   = rem - t * TVEC;
        m[j]   = (e < SLOT4) && (f * 4 < avail * W);
        sof[j] = (unsigned)(((ch * 2 + t) * TSTRIDE + 4 + f * 4) * 4);
        gp[j]  = (t ? targ : pred) + cbase + (size_t)ch * HW + f * 4;
    }
    const unsigned smbase = (unsigned)__cvta_generic_to_shared(sm);

    float acc[ND][3];
    #pragma unroll
    for (int d = 0; d < ND; d++)
        #pragma unroll
        for (int i = 0; i < 3; i++) acc[d][i] = 0.f;

    // prologue: steps 0 .. DEPTH-2
    #pragma unroll
    for (int s = 0; s < DEPTH - 1; s++) {
        const unsigned bo = (unsigned)(s * CHBUF * 4);
        #pragma unroll
        for (int j = 0; j < NJ; j++)
            if (m[j]) cp16(smbase + bo + sof[j], gp[j] + (size_t)(s * CPS) * HW);
        cp_commit();
    }

    const int c0 = lane * 3;

    #pragma unroll 1
    for (int s = 0; s < NSTEP; s++) {
        if      (s < NSTEP - 2)  cp_wait<DEPTH - 2>();
        else if (s == NSTEP - 2) cp_wait<1>();
        else                     cp_wait<0>();
        __syncthreads();

        // issue step s+DEPTH-1 into buffer (s-1)%DEPTH; safe: ordered after sync(s)
        if (s + DEPTH - 1 < NSTEP) {
            const int sn = s + DEPTH - 1;
            const unsigned bo = (unsigned)((sn % DEPTH) * CHBUF * 4);
            #pragma unroll
            for (int j = 0; j < NJ; j++)
                if (m[j]) cp16(smbase + bo + sof[j], gp[j] + (size_t)(sn * CPS) * HW);
            cp_commit();
        }

        const float* bp = sm + (s % DEPTH) * CHBUF;
        #pragma unroll
        for (int ch = 0; ch < CPS; ch++) {
            #pragma unroll
            for (int t = 0; t < 2; t++) {
                const float* sI = bp + (ch * 2 + t) * TSTRIDE + 4;
                float v0[5], v1[7], v2[7];
                const float* r0 = sI + ty * W + c0;
                #pragma unroll
                for (int j = 0; j < 5; j++) v0[j] = r0[j];
                const float* r1 = sI + (ty + 1) * W + c0 - 2;
                #pragma unroll
                for (int j = 0; j < 7; j++) v1[j] = r1[j];
                const float* r2 = sI + (ty + 2) * W + c0 - 2;
                #pragma unroll
                for (int j = 0; j < 7; j++) v2[j] = r2[j];

                #pragma unroll
                for (int i = 0; i < 3; i++) {
                    float ctr = t ? -v0[i] : v0[i];
                    acc[0][i]  = fmaf(ctr, v0[i],     acc[0][i]);
                    acc[1][i]  = fmaf(ctr, v0[i + 1], acc[1][i]);
                    acc[2][i]  = fmaf(ctr, v0[i + 2], acc[2][i]);
                    acc[3][i]  = fmaf(ctr, v1[i],     acc[3][i]);
                    acc[4][i]  = fmaf(ctr, v1[i + 1], acc[4][i]);
                    acc[5][i]  = fmaf(ctr, v1[i + 2], acc[5][i]);
                    acc[6][i]  = fmaf(ctr, v1[i + 3], acc[6][i]);
                    acc[7][i]  = fmaf(ctr, v1[i + 4], acc[7][i]);
                    acc[8][i]  = fmaf(ctr, v2[i],     acc[8][i]);
                    acc[9][i]  = fmaf(ctr, v2[i + 1], acc[9][i]);
                    acc[10][i] = fmaf(ctr, v2[i + 2], acc[10][i]);
                    acc[11][i] = fmaf(ctr, v2[i + 3], acc[11][i]);
                    acc[12][i] = fmaf(ctr, v2[i + 4], acc[12][i]);
                }
            }
        }
    }

    float* slice = g_D + (size_t)(b * NCHUNK + chunk) * ND * HW;
    const int y = gy0 + ty;
    #pragma unroll
    for (int d = 0; d < ND; d++) {
        float* p = slice + (size_t)(d * H + y) * W + c0;
        p[0] = acc[d][0]; p[1] = acc[d][1]; p[2] = acc[d][2];
    }
}

// ---------------------------------------------------------------------------
// Kernel B: collapse 8 chunk slices -> g_Dsum. grid 468 x 256 covers SUM_N4.
__global__ __launch_bounds__(256)
void sum8_kernel() {
    const int i = blockIdx.x * 256 + threadIdx.x;       // float4 index
    const int per_b = ND * HW / 4;                      // 29952
    const int b = i / per_b;
    const int r = i - b * per_b;
    const float4* base = reinterpret_cast<const float4*>(g_D) +
                         (size_t)b * NCHUNK * per_b + r;
    float4 s = make_float4(0.f, 0.f, 0.f, 0.f);
    #pragma unroll
    for (int c = 0; c < NCHUNK; c++) {
        float4 v = base[(size_t)c * per_b];
        s.x += v.x; s.y += v.y; s.z += v.z; s.w += v.w;
    }
    reinterpret_cast<float4*>(g_Dsum)[i] = s;
}

// ---------------------------------------------------------------------------
// Kernel C: gather S from g_Dsum, center, square, atomicAdd to out.
__global__ __launch_bounds__(256)
void loss_kernel(float* __restrict__ out) {
    const int x = blockIdx.x * 32 + threadIdx.x;
    const int y = blockIdx.y * 8  + threadIdx.y;
    const int b = blockIdx.z;

    float lp = 0.f;
    if (x < WP && y < HP) {
        float S[9][9];
        const float* Db = g_Dsum + (size_t)b * ND * HW;
        #pragma unroll
        for (int k = 0; k < 9; k++) {
            const int ky = k/3, kx = k%3;
            #pragma unroll
            for (int l = k; l < 9; l++) {
                const int ly = l/3, lx = l%3;
                const int dy = ly - ky, dx = lx - kx;
                const int didx = (dy == 0) ? dx : (dy == 1 ? 5 + dx : 10 + dx);
                float v = Db[(didx*H + (y + ky))*W + (x + kx)];
                S[k][l] = v;
                S[l][k] = v;
            }
        }
        float r[9], T = 0.f;
        #pragma unroll
        for (int k = 0; k < 9; k++) {
            float s = 0.f;
            #pragma unroll
            for (int l = 0; l < 9; l++) s += S[k][l];
            r[k] = s; T += s;
        }
        const float i9 = 1.f/9.f;
        const float Tc = T * (1.f/81.f);
        #pragma unroll
        for (int k = 0; k < 9; k++)
            #pragma unroll
            for (int l = 0; l < 9; l++) {
                float g = S[k][l] - (r[k] + r[l])*i9 + Tc;
                lp = fmaf(g, g, lp);
            }
    }

    #pragma unroll
    for (int o = 16; o > 0; o >>= 1)
        lp += __shfl_down_sync(0xffffffffu, lp, o);
    __shared__ float ws[8];
    if (threadIdx.x == 0) ws[threadIdx.y] = lp;
    __syncthreads();
    if (threadIdx.x == 0 && threadIdx.y == 0) {
        float s = 0.f;
        #pragma unroll
        for (int w = 0; w < 8; w++) s += ws[w];
        const float NORM = (float)(1.0 / (double)(BATCH * HP * WP * 81));
        atomicAdd(out, s * NORM);
    }
}

// ---------------------------------------------------------------------------
extern "C" void kernel_launch(void* const* d_in, const int* in_sizes, int n_in,
                              void* d_out, int out_size) {
    const float* pred = (const float*)d_in[0];
    const float* targ = (const float*)d_in[1];
    float* out = (float*)d_out;

    {
        dim3 grid(H / TROWS, NCHUNK, BATCH);   // (24, 8, 4) = 768 blocks
        dim3 block(32, TROWS);
        corr_kernel<<<grid, block>>>(pred, targ, out);
    }
    sum8_kernel<<<SUM_N4 / 256, 256>>>();
    {
        dim3 grid(3, 12, BATCH);               // 144 blocks
        dim3 block(32, 8);
        loss_kernel<<<grid, block>>>(out);
    }
}

// round 12
// speedup vs baseline: 1.0555x; 1.0555x over previous
#include <cuda_runtime.h>

// RCLoss = mean((Gram_c(pred_patches) - Gram_c(target_patches))^2), 3x3 patches, C=256.
// Centered Gram is linear in raw Gram; raw-Gram entries are shifted samples of 13
// cross-correlation difference maps D_d = sum_c (p*p_shift - t*t_shift).
// A: corr maps; 6-buffer cp.async ring, 2 stages consumed per barrier.
// B: sum 8 chunk slices -> g_Dsum. C: gather+center+MSE, atomicAdd to out.

#define BATCH   4
#define CH      256
#define H       96
#define W       96
#define HW      (H*W)
#define ND      13
#define HP      94
#define WP      94
#define NCHUNK  8
#define CCHUNK  32
#define NPAIR   (CCHUNK/2)            // 16

#define TROWS     4                   // output rows per block
#define SROWS     6                   // staged rows
#define TFLOATS   (SROWS*W)           // 576
#define TVEC      (TFLOATS/4)         // 144 float4 per tensor
#define TSTRIDE   (TFLOATS+8)         // +4 front guard (16B align) +4 back
#define BUFSTRIDE (2*TSTRIDE)         // 1168 floats: pred+targ for one channel
#define DEPTH     6                   // single-channel buffers in the ring

#define SUM_N4   (BATCH*ND*HW/4)      // 119808 float4s

__device__ float g_D[BATCH*NCHUNK*ND*HW];     // per-chunk slices
__device__ float g_Dsum[BATCH*ND*HW];         // chunk-summed maps (1.9MB)

__device__ __forceinline__ void cp16(unsigned saddr, const float* g) {
    asm volatile("cp.async.cg.shared.global [%0], [%1], 16;\n" :: "r"(saddr), "l"(g));
}
__device__ __forceinline__ void cp_commit() {
    asm volatile("cp.async.commit_group;\n" ::: "memory");
}
template<int N> __device__ __forceinline__ void cp_wait() {
    asm volatile("cp.async.wait_group %0;\n" :: "n"(N) : "memory");
}

// ---------------------------------------------------------------------------
// One channel-stage of correlation accumulation from smem buffer sIbase.
__device__ __forceinline__ void corr_stage(const float* __restrict__ bp,
                                           int ty, int c0, float acc[ND][3]) {
    #pragma unroll
    for (int t = 0; t < 2; t++) {
        const float* sI = bp + t * TSTRIDE + 4;
        float v0[5], v1[7], v2[7];
        const float* r0 = sI + ty * W + c0;
        #pragma unroll
        for (int j = 0; j < 5; j++) v0[j] = r0[j];
        const float* r1 = sI + (ty + 1) * W + c0 - 2;
        #pragma unroll
        for (int j = 0; j < 7; j++) v1[j] = r1[j];
        const float* r2 = sI + (ty + 2) * W + c0 - 2;
        #pragma unroll
        for (int j = 0; j < 7; j++) v2[j] = r2[j];

        #pragma unroll
        for (int i = 0; i < 3; i++) {
            float ctr = t ? -v0[i] : v0[i];
            acc[0][i]  = fmaf(ctr, v0[i],     acc[0][i]);
            acc[1][i]  = fmaf(ctr, v0[i + 1], acc[1][i]);
            acc[2][i]  = fmaf(ctr, v0[i + 2], acc[2][i]);
            acc[3][i]  = fmaf(ctr, v1[i],     acc[3][i]);
            acc[4][i]  = fmaf(ctr, v1[i + 1], acc[4][i]);
            acc[5][i]  = fmaf(ctr, v1[i + 2], acc[5][i]);
            acc[6][i]  = fmaf(ctr, v1[i + 3], acc[6][i]);
            acc[7][i]  = fmaf(ctr, v1[i + 4], acc[7][i]);
            acc[8][i]  = fmaf(ctr, v2[i],     acc[8][i]);
            acc[9][i]  = fmaf(ctr, v2[i + 1], acc[9][i]);
            acc[10][i] = fmaf(ctr, v2[i + 2], acc[10][i]);
            acc[11][i] = fmaf(ctr, v2[i + 3], acc[11][i]);
            acc[12][i] = fmaf(ctr, v2[i + 4], acc[12][i]);
        }
    }
}

// ---------------------------------------------------------------------------
// Kernel A. grid (24, NCHUNK, BATCH) = 768 blocks, block (32, 4).
__global__ __launch_bounds__(128, 6)
void corr_kernel(const float* __restrict__ pred, const float* __restrict__ targ,
                 float* __restrict__ out) {
    __shared__ __align__(16) float sm[DEPTH * BUFSTRIDE];

    const int lane  = threadIdx.x;
    const int ty    = threadIdx.y;            // 0..3, warp == output row
    const int tid   = ty * 32 + lane;
    const int gy0   = blockIdx.x * TROWS;
    const int chunk = blockIdx.y;
    const int b     = blockIdx.z;

    if (tid == 0 && gy0 == 0 && chunk == 0 && b == 0) out[0] = 0.f;

    const int avail = (gy0 + SROWS <= H) ? SROWS : (H - gy0);   // 6 or 4

    if (avail < SROWS) {   // zero unused staged rows once in every buffer
        const int zfl = (SROWS - avail) * W;                     // 192
        for (int i = tid; i < DEPTH * 2 * zfl; i += 128) {
            int buf = i / (2 * zfl);
            int r   = i - buf * (2 * zfl);
            int t   = r / zfl;
            int f   = r - t * zfl;
            sm[buf * BUFSTRIDE + t * TSTRIDE + 4 + avail * W + f] = 0.f;
        }
    }

    // Flat staging: 2*TVEC = 288 float4 slots per stage, 128 threads, 3 slots.
    const size_t cbase = (size_t)(b * CH + chunk * CCHUNK) * HW + (size_t)gy0 * W;
    unsigned     sof[3];
    const float* gp[3];
    bool         m[3];
    #pragma unroll
    for (int j = 0; j < 3; j++) {
        int  e = tid + 128 * j;
        int  t = (e >= TVEC) ? 1 : 0;
        int  f = e - t * TVEC;
        m[j]   = (e < 2 * TVEC) && (f * 4 < avail * W);
        sof[j] = (unsigned)((t * TSTRIDE + 4 + f * 4) * 4);
        gp[j]  = (t ? targ : pred) + cbase + f * 4;
    }
    const unsigned smbase = (unsigned)__cvta_generic_to_shared(sm);

    float acc[ND][3];
    #pragma unroll
    for (int d = 0; d < ND; d++)
        #pragma unroll
        for (int i = 0; i < 3; i++) acc[d][i] = 0.f;

    // prologue: stages 0..3 into buffers 0..3 (one commit group each)
    #pragma unroll
    for (int s = 0; s < 4; s++) {
        const unsigned bo = (unsigned)(s * BUFSTRIDE * 4);
        #pragma unroll
        for (int j = 0; j < 3; j++)
            if (m[j]) cp16(smbase + bo + sof[j], gp[j] + (size_t)s * HW);
        cp_commit();
    }

    const int c0 = lane * 3;
    int bb = 0;                               // buffer index of this pair (0,2,4,...)

    #pragma unroll 1
    for (int k = 0; k < NPAIR; k++) {
        if (k < NPAIR - 1) cp_wait<2>(); else cp_wait<0>();
        __syncthreads();

        // refill stages 2k+4, 2k+5 into buffers (bb+4)%6, (bb+5)%6 —
        // those were consumed at pair k-1, finished before this sync.
        if (k < NPAIR - 2) {
            const int rb = (bb >= 2) ? bb - 2 : bb + 4;
            const int sn = 2 * k + 4;
            #pragma unroll
            for (int q = 0; q < 2; q++) {
                const unsigned bo = (unsigned)((rb + q) * BUFSTRIDE * 4);
                #pragma unroll
                for (int j = 0; j < 3; j++)
                    if (m[j]) cp16(smbase + bo + sof[j], gp[j] + (size_t)(sn + q) * HW);
                cp_commit();
            }
        }

        corr_stage(sm + bb * BUFSTRIDE,       ty, c0, acc);
        corr_stage(sm + (bb + 1) * BUFSTRIDE, ty, c0, acc);

        bb += 2;
        if (bb == DEPTH) bb = 0;
    }

    float* slice = g_D + (size_t)(b * NCHUNK + chunk) * ND * HW;
    const int y = gy0 + ty;
    #pragma unroll
    for (int d = 0; d < ND; d++) {
        float* p = slice + (size_t)(d * H + y) * W + c0;
        p[0] = acc[d][0]; p[1] = acc[d][1]; p[2] = acc[d][2];
    }
}

// ---------------------------------------------------------------------------
// Kernel B: collapse 8 chunk slices -> g_Dsum. grid 468 x 256 covers SUM_N4.
__global__ __launch_bounds__(256)
void sum8_kernel() {
    const int i = blockIdx.x * 256 + threadIdx.x;       // float4 index
    const int per_b = ND * HW / 4;                      // 29952
    const int b = i / per_b;
    const int r = i - b * per_b;
    const float4* base = reinterpret_cast<const float4*>(g_D) +
                         (size_t)b * NCHUNK * per_b + r;
    float4 s = make_float4(0.f, 0.f, 0.f, 0.f);
    #pragma unroll
    for (int c = 0; c < NCHUNK; c++) {
        float4 v = base[(size_t)c * per_b];
        s.x += v.x; s.y += v.y; s.z += v.z; s.w += v.w;
    }
    reinterpret_cast<float4*>(g_Dsum)[i] = s;
}

// ---------------------------------------------------------------------------
// Kernel C: gather S from g_Dsum, center, square, atomicAdd to out.
__global__ __launch_bounds__(256)
void loss_kernel(float* __restrict__ out) {
    const int x = blockIdx.x * 32 + threadIdx.x;
    const int y = blockIdx.y * 8  + threadIdx.y;
    const int b = blockIdx.z;

    float lp = 0.f;
    if (x < WP && y < HP) {
        float S[9][9];
        const float* Db = g_Dsum + (size_t)b * ND * HW;
        #pragma unroll
        for (int k = 0; k < 9; k++) {
            const int ky = k/3, kx = k%3;
            #pragma unroll
            for (int l = k; l < 9; l++) {
                const int ly = l/3, lx = l%3;
                const int dy = ly - ky, dx = lx - kx;
                const int didx = (dy == 0) ? dx : (dy == 1 ? 5 + dx : 10 + dx);
                float v = Db[(didx*H + (y + ky))*W + (x + kx)];
                S[k][l] = v;
                S[l][k] = v;
            }
        }
        float r[9], T = 0.f;
        #pragma unroll
        for (int k = 0; k < 9; k++) {
            float s = 0.f;
            #pragma unroll
            for (int l = 0; l < 9; l++) s += S[k][l];
            r[k] = s; T += s;
        }
        const float i9 = 1.f/9.f;
        const float Tc = T * (1.f/81.f);
        #pragma unroll
        for (int k = 0; k < 9; k++)
            #pragma unroll
            for (int l = 0; l < 9; l++) {
                float g = S[k][l] - (r[k] + r[l])*i9 + Tc;
                lp = fmaf(g, g, lp);
            }
    }

    #pragma unroll
    for (int o = 16; o > 0; o >>= 1)
        lp += __shfl_down_sync(0xffffffffu, lp, o);
    __shared__ float ws[8];
    if (threadIdx.x == 0) ws[threadIdx.y] = lp;
    __syncthreads();
    if (threadIdx.x == 0 && threadIdx.y == 0) {
        float s = 0.f;
        #pragma unroll
        for (int w = 0; w < 8; w++) s += ws[w];
        const float NORM = (float)(1.0 / (double)(BATCH * HP * WP * 81));
        atomicAdd(out, s * NORM);
    }
}

// ---------------------------------------------------------------------------
extern "C" void kernel_launch(void* const* d_in, const int* in_sizes, int n_in,
                              void* d_out, int out_size) {
    const float* pred = (const float*)d_in[0];
    const float* targ = (const float*)d_in[1];
    float* out = (float*)d_out;

    {
        dim3 grid(H / TROWS, NCHUNK, BATCH);   // (24, 8, 4) = 768 blocks
        dim3 block(32, TROWS);
        corr_kernel<<<grid, block>>>(pred, targ, out);
    }
    sum8_kernel<<<SUM_N4 / 256, 256>>>();
    {
        dim3 grid(3, 12, BATCH);               // 144 blocks
        dim3 block(32, 8);
        loss_kernel<<<grid, block>>>(out);
    }
}